// round 4
// baseline (speedup 1.0000x reference)
#include <cuda_runtime.h>
#include <stdint.h>
#include <math.h>

#define TT 2048
#define BB 2
#define DD 512
#define HH 8
#define DH 64
#define MAXREL 32
#define SCALE_L2E 0.1803368801111244f   // (DH^-0.5) * log2(e)
#define L2E 1.4426950408889634f

// Scratch (allocation-free rule: __device__ globals)
__device__ float g_Q[BB * TT * DD];
__device__ float g_K[BB * TT * DD];
__device__ float g_V[BB * TT * DD];
__device__ float g_AO[BB * TT * DD];

// ---------------------------------------------------------------------------
// helpers
// ---------------------------------------------------------------------------
__device__ __forceinline__ uint32_t f2tf32(float f) {
    uint32_t r;
    asm("cvt.rna.tf32.f32 %0, %1;" : "=r"(r) : "f"(f));
    return r;
}
__device__ __forceinline__ float ex2(float x) {
    float r;
    asm("ex2.approx.ftz.f32 %0, %1;" : "=f"(r) : "f"(x));
    return r;
}
// D += A(16x8) * B(8x8), tf32 inputs, f32 accum
__device__ __forceinline__ void mma8(float* d, const uint32_t* a, uint32_t b0, uint32_t b1) {
    asm volatile(
        "mma.sync.aligned.m16n8k8.row.col.f32.tf32.tf32.f32 "
        "{%0,%1,%2,%3}, {%4,%5,%6,%7}, {%8,%9}, {%0,%1,%2,%3};"
        : "+f"(d[0]), "+f"(d[1]), "+f"(d[2]), "+f"(d[3])
        : "r"(a[0]), "r"(a[1]), "r"(a[2]), "r"(a[3]), "r"(b0), "r"(b1));
}
__device__ __forceinline__ uint32_t fbits(float f) { return __float_as_uint(f); }

// ---------------------------------------------------------------------------
// GEMM: C[M,N] = X[M,K] @ W[K,N] + bias[N], tf32 mma.
// BM=128, BN=64, BK=32, 128 threads (4 warps, m32n64 warp tiles).
// ---------------------------------------------------------------------------
#define XPAD 36   // == 4 (mod 32)
#define WPAD 72   // == 8 (mod 32)

__global__ __launch_bounds__(128) void gemm_tf32_kernel(
    const float* __restrict__ X, const float* __restrict__ W,
    const float* __restrict__ bias, float* __restrict__ C,
    int M, int N, int K)
{
    __shared__ __align__(16) float Xs[128 * XPAD];
    __shared__ __align__(16) float Ws[32 * WPAD];
    __shared__ float bs[64];

    const int tid = threadIdx.x;
    const int lane = tid & 31;
    const int wid = tid >> 5;        // 0..3
    const int wr = wid * 32;
    const int g = lane >> 2, q4 = lane & 3;
    const int m0 = blockIdx.y * 128;
    const int n0 = blockIdx.x * 64;

    if (tid < 64) bs[tid] = bias[n0 + tid];

    float c[2][8][4];
#pragma unroll
    for (int ss = 0; ss < 2; ss++)
#pragma unroll
        for (int nt = 0; nt < 8; nt++)
#pragma unroll
            for (int j = 0; j < 4; j++) c[ss][nt][j] = 0.0f;

    for (int k0 = 0; k0 < K; k0 += 32) {
        __syncthreads();
        // X tile 128x32 (1024 float4 / 128 threads = 8 iters)
#pragma unroll
        for (int it = 0; it < 8; it++) {
            int i = tid + it * 128;
            int r = i >> 3, c4 = i & 7;
            float4 v = *(const float4*)&X[(size_t)(m0 + r) * K + k0 + c4 * 4];
            float* d = &Xs[r * XPAD + c4 * 4];
            d[0] = __uint_as_float(f2tf32(v.x));
            d[1] = __uint_as_float(f2tf32(v.y));
            d[2] = __uint_as_float(f2tf32(v.z));
            d[3] = __uint_as_float(f2tf32(v.w));
        }
        // W tile 32x64 (512 float4 -> 4 iters)
#pragma unroll
        for (int it = 0; it < 4; it++) {
            int i = tid + it * 128;
            int r = i >> 4, c4 = i & 15;
            float4 v = *(const float4*)&W[(size_t)(k0 + r) * N + n0 + c4 * 4];
            float* d = &Ws[r * WPAD + c4 * 4];
            d[0] = __uint_as_float(f2tf32(v.x));
            d[1] = __uint_as_float(f2tf32(v.y));
            d[2] = __uint_as_float(f2tf32(v.z));
            d[3] = __uint_as_float(f2tf32(v.w));
        }
        __syncthreads();

#pragma unroll
        for (int ks = 0; ks < 4; ks++) {
            uint32_t a[2][4];
            const int ac = q4 + ks * 8;
#pragma unroll
            for (int ss = 0; ss < 2; ss++) {
                const int r = wr + ss * 16 + g;
                a[ss][0] = fbits(Xs[r * XPAD + ac]);
                a[ss][1] = fbits(Xs[(r + 8) * XPAD + ac]);
                a[ss][2] = fbits(Xs[r * XPAD + ac + 4]);
                a[ss][3] = fbits(Xs[(r + 8) * XPAD + ac + 4]);
            }
#pragma unroll
            for (int nt = 0; nt < 8; nt++) {
                uint32_t b0 = fbits(Ws[(ks * 8 + q4) * WPAD + nt * 8 + g]);
                uint32_t b1 = fbits(Ws[(ks * 8 + q4 + 4) * WPAD + nt * 8 + g]);
                mma8(c[0][nt], a[0], b0, b1);
                mma8(c[1][nt], a[1], b0, b1);
            }
        }
    }

#pragma unroll
    for (int ss = 0; ss < 2; ss++) {
        const int r0 = m0 + wr + ss * 16 + g;
#pragma unroll
        for (int nt = 0; nt < 8; nt++) {
            int col = nt * 8 + q4 * 2;
            float2 o0 = make_float2(c[ss][nt][0] + bs[col], c[ss][nt][1] + bs[col + 1]);
            float2 o1 = make_float2(c[ss][nt][2] + bs[col], c[ss][nt][3] + bs[col + 1]);
            *(float2*)&C[(size_t)r0 * N + n0 + col] = o0;
            *(float2*)&C[(size_t)(r0 + 8) * N + n0 + col] = o1;
        }
    }
}

// ---------------------------------------------------------------------------
// Attention (tf32 mma.sync). Grid (T/128, H, B), 128 threads (4 warps, m32).
// No max-subtraction softmax; O accumulates in registers across key tiles.
// ---------------------------------------------------------------------------
#define QPAD 68
#define KPAD 68
#define VPAD 72
#define PPAD 68
#define O_QS 0
#define O_PS (128 * QPAD)
#define O_KS (O_PS + 128 * PPAD)
#define O_VS (O_KS + 64 * KPAD)
#define O_BI (O_VS + 64 * VPAD)
#define ATTN_SMEM_F (O_BI + 68)
#define ATTN_SMEM_B (ATTN_SMEM_F * 4)

__global__ void __launch_bounds__(128, 2) attn_mma_kernel(
    const float* __restrict__ Q, const float* __restrict__ K,
    const float* __restrict__ V, const float* __restrict__ rb,
    float* __restrict__ O)
{
    extern __shared__ float sm[];
    float* Qs = sm + O_QS;
    float* Ps = sm + O_PS;
    float* Ks = sm + O_KS;
    float* Vs = sm + O_VS;
    float* bias_s = sm + O_BI;

    const int tid = threadIdx.x;
    const int lane = tid & 31;
    const int wid = tid >> 5;        // 0..3
    const int wr = wid * 32;
    const int g = lane >> 2, q4 = lane & 3;
    const int q0 = blockIdx.x * 128;
    const int h = blockIdx.y, b = blockIdx.z;
    const int base = b * TT * DD + h * DH;

    if (tid < 2 * MAXREL + 1) bias_s[tid] = rb[h * (2 * MAXREL + 1) + tid] * L2E;

    // Q tile [128 x 64] -> Qs (tf32): 2048 float4 / 128 threads = 16 iters
#pragma unroll
    for (int it = 0; it < 16; it++) {
        int i = tid + it * 128;
        int r = i >> 4, c4 = i & 15;
        float4 v = *(const float4*)&Q[base + (q0 + r) * DD + c4 * 4];
        float* d = &Qs[r * QPAD + c4 * 4];
        d[0] = __uint_as_float(f2tf32(v.x));
        d[1] = __uint_as_float(f2tf32(v.y));
        d[2] = __uint_as_float(f2tf32(v.z));
        d[3] = __uint_as_float(f2tf32(v.w));
    }

    const float blo = rb[h * (2 * MAXREL + 1)] * L2E;
    const float bhi = rb[h * (2 * MAXREL + 1) + 2 * MAXREL] * L2E;

    float o[2][8][4];
#pragma unroll
    for (int ss = 0; ss < 2; ss++)
#pragma unroll
        for (int nt = 0; nt < 8; nt++)
#pragma unroll
            for (int j = 0; j < 4; j++) o[ss][nt][j] = 0.0f;
    float ls[2][2] = {{0.f, 0.f}, {0.f, 0.f}};

    for (int kt = 0; kt < TT / 64; kt++) {
        const int k0 = kt * 64;
        __syncthreads();   // prev PV reads of Ks/Vs/Ps done

        // K and V tiles [64 x 64] (1024 float4 each -> 8 iters each)
#pragma unroll
        for (int it = 0; it < 8; it++) {
            int i = tid + it * 128;
            int r = i >> 4, c4 = i & 15;
            float4 kv = *(const float4*)&K[base + (k0 + r) * DD + c4 * 4];
            float* dk = &Ks[r * KPAD + c4 * 4];
            dk[0] = __uint_as_float(f2tf32(kv.x));
            dk[1] = __uint_as_float(f2tf32(kv.y));
            dk[2] = __uint_as_float(f2tf32(kv.z));
            dk[3] = __uint_as_float(f2tf32(kv.w));
            float4 vv = *(const float4*)&V[base + (k0 + r) * DD + c4 * 4];
            float* dv = &Vs[r * VPAD + c4 * 4];
            dv[0] = __uint_as_float(f2tf32(vv.x));
            dv[1] = __uint_as_float(f2tf32(vv.y));
            dv[2] = __uint_as_float(f2tf32(vv.z));
            dv[3] = __uint_as_float(f2tf32(vv.w));
        }
        __syncthreads();

        // S = Q K^T  (m=128 q, n=64 keys, k=64 d)
        float s[2][8][4];
#pragma unroll
        for (int ss = 0; ss < 2; ss++)
#pragma unroll
            for (int nt = 0; nt < 8; nt++)
#pragma unroll
                for (int j = 0; j < 4; j++) s[ss][nt][j] = 0.0f;

#pragma unroll
        for (int ks = 0; ks < 8; ks++) {
            uint32_t a[2][4];
            const int ac = q4 + ks * 8;
#pragma unroll
            for (int ss = 0; ss < 2; ss++) {
                const int r = wr + ss * 16 + g;
                a[ss][0] = fbits(Qs[r * QPAD + ac]);
                a[ss][1] = fbits(Qs[(r + 8) * QPAD + ac]);
                a[ss][2] = fbits(Qs[r * QPAD + ac + 4]);
                a[ss][3] = fbits(Qs[(r + 8) * QPAD + ac + 4]);
            }
#pragma unroll
            for (int nt = 0; nt < 8; nt++) {
                uint32_t b0 = fbits(Ks[(nt * 8 + g) * KPAD + q4 + ks * 8]);
                uint32_t b1 = fbits(Ks[(nt * 8 + g) * KPAD + q4 + 4 + ks * 8]);
                mma8(s[0][nt], a[0], b0, b1);
                mma8(s[1][nt], a[1], b0, b1);
            }
        }

        // softmax weights: p = exp2(s*scale*l2e + bias*l2e)
        const int dmin = q0 - (k0 + 63);
        const int dmax = q0 + 127 - k0;
        if (dmin >= MAXREL) {
#pragma unroll
            for (int ss = 0; ss < 2; ss++)
#pragma unroll
                for (int nt = 0; nt < 8; nt++)
#pragma unroll
                    for (int j = 0; j < 4; j++)
                        s[ss][nt][j] = ex2(fmaf(s[ss][nt][j], SCALE_L2E, bhi));
        } else if (dmax <= -MAXREL) {
#pragma unroll
            for (int ss = 0; ss < 2; ss++)
#pragma unroll
                for (int nt = 0; nt < 8; nt++)
#pragma unroll
                    for (int j = 0; j < 4; j++)
                        s[ss][nt][j] = ex2(fmaf(s[ss][nt][j], SCALE_L2E, blo));
        } else {
#pragma unroll
            for (int ss = 0; ss < 2; ss++) {
                const int dr0 = q0 + wr + ss * 16 + g;
#pragma unroll
                for (int nt = 0; nt < 8; nt++) {
                    const int c0 = k0 + nt * 8 + q4 * 2;
#pragma unroll
                    for (int j = 0; j < 4; j++) {
                        int rel = (dr0 + ((j >> 1) << 3)) - (c0 + (j & 1));
                        rel = min(max(rel, -MAXREL), MAXREL) + MAXREL;
                        s[ss][nt][j] = ex2(fmaf(s[ss][nt][j], SCALE_L2E, bias_s[rel]));
                    }
                }
            }
        }
#pragma unroll
        for (int ss = 0; ss < 2; ss++)
#pragma unroll
            for (int nt = 0; nt < 8; nt++) {
                ls[ss][0] += s[ss][nt][0] + s[ss][nt][1];
                ls[ss][1] += s[ss][nt][2] + s[ss][nt][3];
            }

        // P -> smem (tf32), layout [128 q][64 keys]
#pragma unroll
        for (int ss = 0; ss < 2; ss++) {
            const int r = wr + ss * 16 + g;
#pragma unroll
            for (int nt = 0; nt < 8; nt++) {
                int col = nt * 8 + q4 * 2;
                float2 p0 = make_float2(__uint_as_float(f2tf32(s[ss][nt][0])),
                                        __uint_as_float(f2tf32(s[ss][nt][1])));
                float2 p1 = make_float2(__uint_as_float(f2tf32(s[ss][nt][2])),
                                        __uint_as_float(f2tf32(s[ss][nt][3])));
                *(float2*)&Ps[r * PPAD + col] = p0;
                *(float2*)&Ps[(r + 8) * PPAD + col] = p1;
            }
        }
        __syncthreads();

        // O += P V  (m=128 q, n=64 d, k=64 keys)
#pragma unroll
        for (int ks = 0; ks < 8; ks++) {
            uint32_t a[2][4];
            const int ac = q4 + ks * 8;
#pragma unroll
            for (int ss = 0; ss < 2; ss++) {
                const int r = wr + ss * 16 + g;
                a[ss][0] = fbits(Ps[r * PPAD + ac]);
                a[ss][1] = fbits(Ps[(r + 8) * PPAD + ac]);
                a[ss][2] = fbits(Ps[r * PPAD + ac + 4]);
                a[ss][3] = fbits(Ps[(r + 8) * PPAD + ac + 4]);
            }
#pragma unroll
            for (int nt = 0; nt < 8; nt++) {
                uint32_t b0 = fbits(Vs[(ks * 8 + q4) * VPAD + nt * 8 + g]);
                uint32_t b1 = fbits(Vs[(ks * 8 + q4 + 4) * VPAD + nt * 8 + g]);
                mma8(o[0][nt], a[0], b0, b1);
                mma8(o[1][nt], a[1], b0, b1);
            }
        }
    }

    // reduce row sums across the 4 lanes of each quad
#pragma unroll
    for (int ss = 0; ss < 2; ss++) {
#pragma unroll
        for (int j = 0; j < 2; j++) {
            ls[ss][j] += __shfl_xor_sync(0xffffffffu, ls[ss][j], 1);
            ls[ss][j] += __shfl_xor_sync(0xffffffffu, ls[ss][j], 2);
        }
    }

#pragma unroll
    for (int ss = 0; ss < 2; ss++) {
        const float inv0 = 1.0f / ls[ss][0];
        const float inv1 = 1.0f / ls[ss][1];
        const int r0 = q0 + wr + ss * 16 + g;
#pragma unroll
        for (int nt = 0; nt < 8; nt++) {
            int col = nt * 8 + q4 * 2;
            float2 o0 = make_float2(o[ss][nt][0] * inv0, o[ss][nt][1] * inv0);
            float2 o1 = make_float2(o[ss][nt][2] * inv1, o[ss][nt][3] * inv1);
            *(float2*)&O[base + r0 * DD + col] = o0;
            *(float2*)&O[base + (r0 + 8) * DD + col] = o1;
        }
    }
}

// ---------------------------------------------------------------------------
extern "C" void kernel_launch(void* const* d_in, const int* in_sizes, int n_in,
                              void* d_out, int out_size)
{
    const float* hs = (const float*)d_in[0];
    const float* Wq = (const float*)d_in[1];
    const float* bq = (const float*)d_in[2];
    const float* Wk = (const float*)d_in[3];
    const float* bk = (const float*)d_in[4];
    const float* Wv = (const float*)d_in[5];
    const float* bv = (const float*)d_in[6];
    const float* Wo = (const float*)d_in[7];
    const float* bo = (const float*)d_in[8];
    const float* rb = (const float*)d_in[9];

    float *pQ, *pK, *pV, *pA;
    cudaGetSymbolAddress((void**)&pQ, g_Q);
    cudaGetSymbolAddress((void**)&pK, g_K);
    cudaGetSymbolAddress((void**)&pV, g_V);
    cudaGetSymbolAddress((void**)&pA, g_AO);

    static int smem_set = 0;
    if (!smem_set) {
        cudaFuncSetAttribute(attn_mma_kernel,
                             cudaFuncAttributeMaxDynamicSharedMemorySize, ATTN_SMEM_B);
        smem_set = 1;
    }

    const int M = BB * TT;   // 4096
    dim3 gg(DD / 64, M / 128);

    gemm_tf32_kernel<<<gg, 128>>>(hs, Wq, bq, pQ, M, DD, DD);
    gemm_tf32_kernel<<<gg, 128>>>(hs, Wk, bk, pK, M, DD, DD);
    gemm_tf32_kernel<<<gg, 128>>>(hs, Wv, bv, pV, M, DD, DD);

    attn_mma_kernel<<<dim3(TT / 128, HH, BB), 128, ATTN_SMEM_B>>>(pQ, pK, pV, rb, pA);

    gemm_tf32_kernel<<<gg, 128>>>(pA, Wo, bo, (float*)d_out, M, DD, DD);
}

// round 5
// speedup vs baseline: 1.4434x; 1.4434x over previous
#include <cuda_runtime.h>
#include <stdint.h>
#include <math.h>

#define TT 2048
#define BB 2
#define DD 512
#define HH 8
#define DH 64
#define MAXREL 32
#define SCALE_L2E 0.1803368801111244f   // (DH^-0.5) * log2(e)
#define L2E 1.4426950408889634f
#define NT (TT / 64)

// Scratch (allocation-free rule: __device__ globals)
__device__ float g_Q[BB * TT * DD];
__device__ float g_K[BB * TT * DD];
__device__ float g_V[BB * TT * DD];
__device__ float g_AO[BB * TT * DD];

// ---------------------------------------------------------------------------
// helpers
// ---------------------------------------------------------------------------
__device__ __forceinline__ uint32_t f2tf32(float f) {
    uint32_t r;
    asm("cvt.rna.tf32.f32 %0, %1;" : "=r"(r) : "f"(f));
    return r;
}
__device__ __forceinline__ float tf32r(float f) { return __uint_as_float(f2tf32(f)); }
__device__ __forceinline__ float ex2(float x) {
    float r;
    asm("ex2.approx.ftz.f32 %0, %1;" : "=f"(r) : "f"(x));
    return r;
}
__device__ __forceinline__ void mma8(float* d, const uint32_t* a, uint32_t b0, uint32_t b1) {
    asm volatile(
        "mma.sync.aligned.m16n8k8.row.col.f32.tf32.tf32.f32 "
        "{%0,%1,%2,%3}, {%4,%5,%6,%7}, {%8,%9}, {%0,%1,%2,%3};"
        : "+f"(d[0]), "+f"(d[1]), "+f"(d[2]), "+f"(d[3])
        : "r"(a[0]), "r"(a[1]), "r"(a[2]), "r"(a[3]), "r"(b0), "r"(b1));
}
__device__ __forceinline__ uint32_t fbits(float f) { return __float_as_uint(f); }
__device__ __forceinline__ uint32_t smem_u32(const void* p) {
    uint32_t a;
    asm("{ .reg .u64 t; cvta.to.shared.u64 t, %1; cvt.u32.u64 %0, t; }" : "=r"(a) : "l"(p));
    return a;
}
__device__ __forceinline__ void cpasync16(uint32_t dst, const void* src) {
    asm volatile("cp.async.cg.shared.global [%0], [%1], 16;" :: "r"(dst), "l"(src));
}
#define CP_COMMIT() asm volatile("cp.async.commit_group;" ::: "memory")
#define CP_WAIT1()  asm volatile("cp.async.wait_group 1;" ::: "memory")

// ---------------------------------------------------------------------------
// GEMM: C[M,N] = X[M,K] @ W[K,N] + bias[N], tf32 mma (R3 structure).
// round_out != 0 -> store tf32-RNA-rounded outputs (for Q/K/V feeding attn).
// ---------------------------------------------------------------------------
#define XPAD 36   // == 4 (mod 32)
#define WPAD 72   // == 8 (mod 32)

__global__ __launch_bounds__(256) void gemm_tf32_kernel(
    const float* __restrict__ X, const float* __restrict__ W,
    const float* __restrict__ bias, float* __restrict__ C,
    int M, int N, int K, int round_out)
{
    __shared__ __align__(16) float Xs[128 * XPAD];
    __shared__ __align__(16) float Ws[32 * WPAD];
    __shared__ float bs[64];

    const int tid = threadIdx.x;
    const int lane = tid & 31;
    const int wid = tid >> 5;
    const int wr = wid * 16;
    const int g = lane >> 2, q4 = lane & 3;
    const int m0 = blockIdx.y * 128;
    const int n0 = blockIdx.x * 64;

    if (tid < 64) bs[tid] = bias[n0 + tid];

    float c[8][4];
#pragma unroll
    for (int nt = 0; nt < 8; nt++)
#pragma unroll
        for (int j = 0; j < 4; j++) c[nt][j] = 0.0f;

    for (int k0 = 0; k0 < K; k0 += 32) {
        __syncthreads();
#pragma unroll
        for (int it = 0; it < 4; it++) {
            int i = tid + it * 256;
            int r = i >> 3, c4 = i & 7;
            float4 v = *(const float4*)&X[(size_t)(m0 + r) * K + k0 + c4 * 4];
            float* d = &Xs[r * XPAD + c4 * 4];
            d[0] = tf32r(v.x); d[1] = tf32r(v.y); d[2] = tf32r(v.z); d[3] = tf32r(v.w);
        }
#pragma unroll
        for (int it = 0; it < 2; it++) {
            int i = tid + it * 256;
            int r = i >> 4, c4 = i & 15;
            float4 v = *(const float4*)&W[(size_t)(k0 + r) * N + n0 + c4 * 4];
            float* d = &Ws[r * WPAD + c4 * 4];
            d[0] = tf32r(v.x); d[1] = tf32r(v.y); d[2] = tf32r(v.z); d[3] = tf32r(v.w);
        }
        __syncthreads();

#pragma unroll
        for (int ks = 0; ks < 4; ks++) {
            uint32_t a[4];
            const int ac = q4 + ks * 8;
            a[0] = fbits(Xs[(wr + g) * XPAD + ac]);
            a[1] = fbits(Xs[(wr + g + 8) * XPAD + ac]);
            a[2] = fbits(Xs[(wr + g) * XPAD + ac + 4]);
            a[3] = fbits(Xs[(wr + g + 8) * XPAD + ac + 4]);
#pragma unroll
            for (int nt = 0; nt < 8; nt++) {
                uint32_t b0 = fbits(Ws[(ks * 8 + q4) * WPAD + nt * 8 + g]);
                uint32_t b1 = fbits(Ws[(ks * 8 + q4 + 4) * WPAD + nt * 8 + g]);
                mma8(c[nt], a, b0, b1);
            }
        }
    }

    const int r0 = m0 + wr + g;
#pragma unroll
    for (int nt = 0; nt < 8; nt++) {
        int col = nt * 8 + q4 * 2;
        float o00 = c[nt][0] + bs[col], o01 = c[nt][1] + bs[col + 1];
        float o10 = c[nt][2] + bs[col], o11 = c[nt][3] + bs[col + 1];
        if (round_out) {
            o00 = tf32r(o00); o01 = tf32r(o01); o10 = tf32r(o10); o11 = tf32r(o11);
        }
        *(float2*)&C[(size_t)r0 * N + n0 + col] = make_float2(o00, o01);
        *(float2*)&C[(size_t)(r0 + 8) * N + n0 + col] = make_float2(o10, o11);
    }
}

// ---------------------------------------------------------------------------
// Attention (tf32 mma.sync). Grid (T/128, H, B), 256 threads (8 warps, m16).
// cp.async double-buffered K/V (pre-rounded tf32 in GMEM); register-P via
// shuffles; no max-subtraction softmax; O in registers across key tiles.
// ---------------------------------------------------------------------------
#define QPAD 68
#define KPAD 68
#define VPAD 72
#define O_QS 0
#define KBUF (64 * KPAD)           // 4352
#define VBUF (64 * VPAD)           // 4608
#define O_KV (128 * QPAD)          // 8704
#define O_BI (O_KV + 2 * (KBUF + VBUF))
#define ATTN_SMEM_F (O_BI + 68)
#define ATTN_SMEM_B (ATTN_SMEM_F * 4)

__global__ void __launch_bounds__(256, 2) attn_mma_kernel(
    const float* __restrict__ Q, const float* __restrict__ K,
    const float* __restrict__ V, const float* __restrict__ rb,
    float* __restrict__ O)
{
    extern __shared__ float sm[];
    float* Qs = sm + O_QS;
    float* bias_s = sm + O_BI;
    const uint32_t smb = smem_u32(sm);

    const int tid = threadIdx.x;
    const int lane = tid & 31;
    const int wid = tid >> 5;
    const int wr = wid * 16;
    const int g = lane >> 2, q4 = lane & 3;
    const int q0 = blockIdx.x * 128;
    const int h = blockIdx.y, b = blockIdx.z;
    const int base = b * TT * DD + h * DH;

    // issue cp.async for key tile kt into buffer bf
    auto issue_tile = [&](int kt, int bf) {
        const int k0 = kt * 64;
        const uint32_t kdst = smb + (O_KV + bf * (KBUF + VBUF)) * 4;
        const uint32_t vdst = kdst + KBUF * 4;
#pragma unroll
        for (int it = 0; it < 4; it++) {
            int i = tid + it * 256;
            int r = i >> 4, c4 = i & 15;
            cpasync16(kdst + (r * KPAD + c4 * 4) * 4, &K[base + (k0 + r) * DD + c4 * 4]);
            cpasync16(vdst + (r * VPAD + c4 * 4) * 4, &V[base + (k0 + r) * DD + c4 * 4]);
        }
    };

    issue_tile(0, 0);
    CP_COMMIT();

    if (tid < 2 * MAXREL + 1) bias_s[tid] = rb[h * (2 * MAXREL + 1) + tid] * L2E;
    const float blo = rb[h * (2 * MAXREL + 1)] * L2E;
    const float bhi = rb[h * (2 * MAXREL + 1) + 2 * MAXREL] * L2E;

    // Q tile [128 x 64] -> Qs (already tf32-rounded in GMEM)
#pragma unroll
    for (int it = 0; it < 8; it++) {
        int i = tid + it * 256;
        int r = i >> 4, c4 = i & 15;
        float4 v = *(const float4*)&Q[base + (q0 + r) * DD + c4 * 4];
        *(float4*)&Qs[r * QPAD + c4 * 4] = v;
    }

    float o[8][4];
#pragma unroll
    for (int nt = 0; nt < 8; nt++)
#pragma unroll
        for (int j = 0; j < 4; j++) o[nt][j] = 0.0f;
    float ls0 = 0.0f, ls1 = 0.0f;

    const int dr0 = q0 + wr + g;
    const int src0 = g * 4 + (q4 >> 1);
    const int src1 = src0 + 2;
    const bool oddq = (q4 & 1);

    for (int kt = 0; kt < NT; kt++) {
        const int k0 = kt * 64;
        const int bf = kt & 1;
        const float* Ks = sm + O_KV + bf * (KBUF + VBUF);
        const float* Vs = Ks + KBUF;

        if (kt + 1 < NT) issue_tile(kt + 1, bf ^ 1);
        CP_COMMIT();
        CP_WAIT1();
        __syncthreads();

        // S = Q K^T  (m=128 q, n=64 keys, k=64 d)
        float s[8][4];
#pragma unroll
        for (int nt = 0; nt < 8; nt++)
#pragma unroll
            for (int j = 0; j < 4; j++) s[nt][j] = 0.0f;

#pragma unroll
        for (int ks = 0; ks < 8; ks++) {
            uint32_t a[4];
            const int ac = q4 + ks * 8;
            a[0] = fbits(Qs[(wr + g) * QPAD + ac]);
            a[1] = fbits(Qs[(wr + g + 8) * QPAD + ac]);
            a[2] = fbits(Qs[(wr + g) * QPAD + ac + 4]);
            a[3] = fbits(Qs[(wr + g + 8) * QPAD + ac + 4]);
#pragma unroll
            for (int nt = 0; nt < 8; nt++) {
                uint32_t b0 = fbits(Ks[(nt * 8 + g) * KPAD + q4 + ks * 8]);
                uint32_t b1 = fbits(Ks[(nt * 8 + g) * KPAD + q4 + 4 + ks * 8]);
                mma8(s[nt], a, b0, b1);
            }
        }

        // softmax weights: p = exp2(s*scale*l2e + bias*l2e)
        const int dmin = q0 - (k0 + 63);
        const int dmax = q0 + 127 - k0;
        if (dmin >= MAXREL) {
#pragma unroll
            for (int nt = 0; nt < 8; nt++)
#pragma unroll
                for (int j = 0; j < 4; j++) s[nt][j] = ex2(fmaf(s[nt][j], SCALE_L2E, bhi));
        } else if (dmax <= -MAXREL) {
#pragma unroll
            for (int nt = 0; nt < 8; nt++)
#pragma unroll
                for (int j = 0; j < 4; j++) s[nt][j] = ex2(fmaf(s[nt][j], SCALE_L2E, blo));
        } else {
#pragma unroll
            for (int nt = 0; nt < 8; nt++) {
                const int c0 = k0 + nt * 8 + q4 * 2;
#pragma unroll
                for (int j = 0; j < 4; j++) {
                    int rel = (dr0 + ((j >> 1) << 3)) - (c0 + (j & 1));
                    rel = min(max(rel, -MAXREL), MAXREL) + MAXREL;
                    s[nt][j] = ex2(fmaf(s[nt][j], SCALE_L2E, bias_s[rel]));
                }
            }
        }
#pragma unroll
        for (int nt = 0; nt < 8; nt++) {
            ls0 += s[nt][0] + s[nt][1];
            ls1 += s[nt][2] + s[nt][3];
            s[nt][0] = tf32r(s[nt][0]);
            s[nt][1] = tf32r(s[nt][1]);
            s[nt][2] = tf32r(s[nt][2]);
            s[nt][3] = tf32r(s[nt][3]);
        }

        // O += P V: A-fragments of P built from S C-fragments via shuffles
#pragma unroll
        for (int ks = 0; ks < 8; ks++) {
            float v0 = __shfl_sync(0xffffffffu, s[ks][0], src0);
            float v1 = __shfl_sync(0xffffffffu, s[ks][1], src0);
            float v2 = __shfl_sync(0xffffffffu, s[ks][2], src0);
            float v3 = __shfl_sync(0xffffffffu, s[ks][3], src0);
            float w0 = __shfl_sync(0xffffffffu, s[ks][0], src1);
            float w1 = __shfl_sync(0xffffffffu, s[ks][1], src1);
            float w2 = __shfl_sync(0xffffffffu, s[ks][2], src1);
            float w3 = __shfl_sync(0xffffffffu, s[ks][3], src1);
            uint32_t a[4];
            a[0] = fbits(oddq ? v1 : v0);
            a[1] = fbits(oddq ? v3 : v2);
            a[2] = fbits(oddq ? w1 : w0);
            a[3] = fbits(oddq ? w3 : w2);
#pragma unroll
            for (int nt = 0; nt < 8; nt++) {
                uint32_t b0 = fbits(Vs[(ks * 8 + q4) * VPAD + nt * 8 + g]);
                uint32_t b1 = fbits(Vs[(ks * 8 + q4 + 4) * VPAD + nt * 8 + g]);
                mma8(o[nt], a, b0, b1);
            }
        }
        __syncthreads();   // all warps done with this buffer before it is refilled
    }

    // reduce row sums across the 4 lanes of each quad
    ls0 += __shfl_xor_sync(0xffffffffu, ls0, 1);
    ls0 += __shfl_xor_sync(0xffffffffu, ls0, 2);
    ls1 += __shfl_xor_sync(0xffffffffu, ls1, 1);
    ls1 += __shfl_xor_sync(0xffffffffu, ls1, 2);
    const float inv0 = 1.0f / ls0;
    const float inv1 = 1.0f / ls1;

    const int r0 = q0 + wr + g;
#pragma unroll
    for (int nt = 0; nt < 8; nt++) {
        int col = nt * 8 + q4 * 2;
        float2 o0 = make_float2(tf32r(o[nt][0] * inv0), tf32r(o[nt][1] * inv0));
        float2 o1 = make_float2(tf32r(o[nt][2] * inv1), tf32r(o[nt][3] * inv1));
        *(float2*)&O[base + r0 * DD + col] = o0;
        *(float2*)&O[base + (r0 + 8) * DD + col] = o1;
    }
}

// ---------------------------------------------------------------------------
extern "C" void kernel_launch(void* const* d_in, const int* in_sizes, int n_in,
                              void* d_out, int out_size)
{
    const float* hs = (const float*)d_in[0];
    const float* Wq = (const float*)d_in[1];
    const float* bq = (const float*)d_in[2];
    const float* Wk = (const float*)d_in[3];
    const float* bk = (const float*)d_in[4];
    const float* Wv = (const float*)d_in[5];
    const float* bv = (const float*)d_in[6];
    const float* Wo = (const float*)d_in[7];
    const float* bo = (const float*)d_in[8];
    const float* rb = (const float*)d_in[9];

    float *pQ, *pK, *pV, *pA;
    cudaGetSymbolAddress((void**)&pQ, g_Q);
    cudaGetSymbolAddress((void**)&pK, g_K);
    cudaGetSymbolAddress((void**)&pV, g_V);
    cudaGetSymbolAddress((void**)&pA, g_AO);

    static int smem_set = 0;
    if (!smem_set) {
        cudaFuncSetAttribute(attn_mma_kernel,
                             cudaFuncAttributeMaxDynamicSharedMemorySize, ATTN_SMEM_B);
        smem_set = 1;
    }

    const int M = BB * TT;   // 4096
    dim3 gg(DD / 64, M / 128);

    gemm_tf32_kernel<<<gg, 256>>>(hs, Wq, bq, pQ, M, DD, DD, 1);
    gemm_tf32_kernel<<<gg, 256>>>(hs, Wk, bk, pK, M, DD, DD, 1);
    gemm_tf32_kernel<<<gg, 256>>>(hs, Wv, bv, pV, M, DD, DD, 1);

    attn_mma_kernel<<<dim3(TT / 128, HH, BB), 256, ATTN_SMEM_B>>>(pQ, pK, pV, rb, pA);

    gemm_tf32_kernel<<<gg, 256>>>(pA, Wo, bo, (float*)d_out, M, DD, DD, 0);
}